// round 14
// baseline (speedup 1.0000x reference)
#include <cuda_runtime.h>

#define NB 8
#define NS 4096
#define NH 8
#define ND 128
#define ROW 1024                      // floats per token-row
#define F8_PER_ROW 128                // float8 (32B) per row
#define MAX_TOTAL (NB * NS)           // 32768 rows per cache
#define CACHE_F (MAX_TOTAL * ROW)     // floats per cache
#define CACHE_V8 (MAX_TOTAL * F8_PER_ROW)   // 4194304 float8 per cache
#define TOTAL_V8 (2 * CACHE_V8)             // 8388608 float8
#define THREADS 256
#define F8_PER_WARP 128               // one full token-row per warp (4KB)
#define WARPS_PER_BLOCK (THREADS / 32)
#define BLOCKS (TOTAL_V8 / (F8_PER_WARP * WARPS_PER_BLOCK))   // 8192
#define FULL 0xffffffffu

// 256-bit transaction probe. Same algorithm as the best (R12) kernel, but
// each warp owns one full token-row (128 float8); lane l handles float8
// indices {0,32,64,96}+l via ld/st.global.v8.f32 (LDG.256/STG.256, sm_100+).
// Fully coalesced (warp covers contiguous 1KB per instruction), MLP=4,
// half the instruction/wavefront count of the float4 version.
__device__ __forceinline__ void ldg256_cs(const float* p, float4& a, float4& b) {
    asm volatile("ld.global.cs.v8.f32 {%0,%1,%2,%3,%4,%5,%6,%7}, [%8];"
        : "=f"(a.x), "=f"(a.y), "=f"(a.z), "=f"(a.w),
          "=f"(b.x), "=f"(b.y), "=f"(b.z), "=f"(b.w)
        : "l"(p));
}
__device__ __forceinline__ void stg256_cs(float* p, const float4& a, const float4& b) {
    asm volatile("st.global.cs.v8.f32 [%0], {%1,%2,%3,%4,%5,%6,%7,%8};"
        :: "l"(p),
           "f"(a.x), "f"(a.y), "f"(a.z), "f"(a.w),
           "f"(b.x), "f"(b.y), "f"(b.z), "f"(b.w)
        : "memory");
}

__global__ void __launch_bounds__(THREADS) pack_kernel(
    const float* __restrict__ k_src,
    const float* __restrict__ v_src,
    const int* __restrict__ seq_lens,
    float* __restrict__ out)
{
    const int lane = threadIdx.x & 31;

    // per-warp cumsum: lane i (i<8) ends with v = sum(seq_lens[0..i])
    int sl = (lane < NB) ? __ldg(seq_lens + lane) : 0;
    int v = sl;
    #pragma unroll
    for (int off = 1; off < NB; off <<= 1) {
        int n = __shfl_up_sync(FULL, v, off);
        if (lane >= off) v += n;
    }
    const int total = __shfl_sync(FULL, v, NB - 1);

    const int gw    = blockIdx.x * WARPS_PER_BLOCK + (threadIdx.x >> 5);
    const int base8 = gw * F8_PER_WARP;           // warp's first float8 index

    const int which = (base8 >= CACHE_V8) ? 1 : 0;
    const int row   = (base8 - which * CACHE_V8) >> 7;   // token-row

    float4 a0, b0, a1, b1, a2, b2, a3, b3;
    if (row < total) {
        int bt = row, bi = 0;
        #pragma unroll
        for (int bb = 1; bb < NB; bb++) {
            int csb = __shfl_sync(FULL, v, bb - 1);
            if (row >= csb) { bi = bb; bt = row - csb; }
        }
        const float* src = (which ? v_src : k_src)
                         + (long long)(bi * NS + bt) * ROW + lane * 8;
        ldg256_cs(src +  0 * 256, a0, b0);        // float8 idx lane + 0
        ldg256_cs(src +  1 * 256, a1, b1);        // float8 idx lane + 32
        ldg256_cs(src +  2 * 256, a2, b2);        // float8 idx lane + 64
        ldg256_cs(src +  3 * 256, a3, b3);        // float8 idx lane + 96
    } else {
        a0 = b0 = a1 = b1 = a2 = b2 = a3 = b3 = make_float4(0.f, 0.f, 0.f, 0.f);
    }

    float* dst = out + (long long)base8 * 8 + lane * 8;
    stg256_cs(dst + 0 * 256, a0, b0);
    stg256_cs(dst + 1 * 256, a1, b1);
    stg256_cs(dst + 2 * 256, a2, b2);
    stg256_cs(dst + 3 * 256, a3, b3);

    // scalar tail outputs (block 0, warp 0) — after the bulk stores
    if (blockIdx.x == 0 && threadIdx.x < 32) {
        float* seq_out = out + 2 * (long long)CACHE_F;  // [NB]
        float* cum_out = seq_out + NB;                   // [NB+1]
        if (lane < NB) {
            seq_out[lane] = (float)sl;
            cum_out[lane + 1] = (float)v;
        }
        if (lane == 0) cum_out[0] = 0.0f;
    }
}

extern "C" void kernel_launch(void* const* d_in, const int* in_sizes, int n_in,
                              void* d_out, int out_size) {
    const float* key_states   = (const float*)d_in[0];
    const float* value_states = (const float*)d_in[1];
    const int*   seq_lens     = (const int*)d_in[2];

    pack_kernel<<<BLOCKS, THREADS>>>(key_states, value_states, seq_lens,
                                     (float*)d_out);
}

// round 15
// speedup vs baseline: 1.0058x; 1.0058x over previous
#include <cuda_runtime.h>

#define NB 8
#define NS 4096
#define NH 8
#define ND 128
#define ROW (NH * ND)                 // 1024 floats per token-row
#define VPR (ROW / 4)                 // 256 float4 per row
#define MAX_TOTAL (NB * NS)           // 32768 rows per cache
#define CACHE_F (MAX_TOTAL * ROW)     // floats per cache
#define CACHE_V (MAX_TOTAL * VPR)     // 8388608 float4 per cache
#define TOTAL_V (2 * CACHE_V)         // 16777216 float4
#define THREADS 256
#define F4_PER_WARP 128               // 4 float4 per thread, warp-interleaved
#define WARPS_PER_BLOCK (THREADS / 32)
#define BLOCKS (TOTAL_V / (F4_PER_WARP * WARPS_PER_BLOCK))   // 16384
#define FULL 0xffffffffu

// FINAL kernel — measured best across 14 rounds (57.8us kernel, 80.4% of
// 8TB/s HBM spec, total 65.6us, rel_err 0.0).
//
// Design: single fused pass, barrier-free. Every warp independently loads
// seq_lens (32B coalesced; L1-hit after the first warp per SM), computes the
// cumsum with a shuffle scan, resolves its batch via SHFL broadcasts, then
// streams its half token-row: lane l handles base + {0,32,64,96} + l.
// Fully coalesced LDG.128 (.cs, touch-once) with 4 independent loads in
// flight per thread; STG.128 (.wt) write-through bulk stores. 29 regs, no
// smem, no BAR.
//
// Roofline argument: traffic is at the mandatory floor (256MB output writes
// + valid-input reads, ~370MB total per launch) and achieved bandwidth sits
// at the mixed ~2:1 write:read HBM turnaround ceiling (78-80% of spec across
// 8 independent configurations). Compute pipes are idle; nothing further to
// hide or eliminate.
__global__ void __launch_bounds__(THREADS) pack_kernel(
    const float4* __restrict__ k_src,
    const float4* __restrict__ v_src,
    const int* __restrict__ seq_lens,
    float4* __restrict__ out)
{
    const int lane = threadIdx.x & 31;

    // per-warp cumsum: lane i (i<8) ends with v = sum(seq_lens[0..i])
    int sl = (lane < NB) ? __ldg(seq_lens + lane) : 0;
    int v = sl;
    #pragma unroll
    for (int off = 1; off < NB; off <<= 1) {
        int n = __shfl_up_sync(FULL, v, off);
        if (lane >= off) v += n;
    }
    const int total = __shfl_sync(FULL, v, NB - 1);

    const int gw   = blockIdx.x * WARPS_PER_BLOCK + (threadIdx.x >> 5);
    const int base = gw * F4_PER_WARP;            // warp's first float4 index

    const int which = (base >= CACHE_V) ? 1 : 0;  // whole warp in one cache
    const int j   = base - which * CACHE_V;
    const int row = j >> 8;                        // token-row (shared by all 4 elems)
    const int col = (j & (VPR - 1)) + lane;        // 0 or 128, plus lane

    float4 v0, v1, v2, v3;
    if (row < total) {
        // batch search + offset via shuffle broadcasts of the scan
        int bt = row;                              // t = row - cs[b], cs[0] = 0
        int bi = 0;
        #pragma unroll
        for (int bb = 1; bb < NB; bb++) {
            int csb = __shfl_sync(FULL, v, bb - 1);
            if (row >= csb) { bi = bb; bt = row - csb; }
        }
        const float4* src = (which ? v_src : k_src)
                          + (long long)(bi * NS + bt) * VPR + col;
        v0 = __ldcs(src +  0);
        v1 = __ldcs(src + 32);
        v2 = __ldcs(src + 64);
        v3 = __ldcs(src + 96);
    } else {
        v0 = v1 = v2 = v3 = make_float4(0.f, 0.f, 0.f, 0.f);
    }

    float4* dst = out + base + lane;
    __stwt(dst +  0, v0);
    __stwt(dst + 32, v1);
    __stwt(dst + 64, v2);
    __stwt(dst + 96, v3);

    // scalar tail outputs (block 0, warp 0) — after the bulk stores
    if (blockIdx.x == 0 && threadIdx.x < 32) {
        float* seq_out = (float*)out + 2 * (long long)CACHE_F;  // [NB]
        float* cum_out = seq_out + NB;                           // [NB+1]
        if (lane < NB) {
            seq_out[lane] = (float)sl;
            cum_out[lane + 1] = (float)v;
        }
        if (lane == 0) cum_out[0] = 0.0f;
    }
}

extern "C" void kernel_launch(void* const* d_in, const int* in_sizes, int n_in,
                              void* d_out, int out_size) {
    const float4* key_states   = (const float4*)d_in[0];
    const float4* value_states = (const float4*)d_in[1];
    const int*    seq_lens     = (const int*)d_in[2];

    pack_kernel<<<BLOCKS, THREADS>>>(key_states, value_states, seq_lens,
                                     (float4*)d_out);
}

// round 16
// speedup vs baseline: 1.0103x; 1.0044x over previous
#include <cuda_runtime.h>

#define NB 8
#define NS 4096
#define NH 8
#define ND 128
#define ROW (NH * ND)                 // 1024 floats per token-row
#define VPR (ROW / 4)                 // 256 float4 per row
#define MAX_TOTAL (NB * NS)           // 32768 rows per cache
#define CACHE_F (MAX_TOTAL * ROW)     // floats per cache
#define CACHE_V (MAX_TOTAL * VPR)     // 8388608 float4 per cache
#define TOTAL_V (2 * CACHE_V)         // 16777216 float4
#define THREADS 256
#define F4_PER_WARP 128               // 4 float4 per thread, warp-interleaved
#define WARPS_PER_BLOCK (THREADS / 32)
#define BLOCKS (TOTAL_V / (F4_PER_WARP * WARPS_PER_BLOCK))   // 16384
#define FULL 0xffffffffu

// FINAL kernel — best measured config across 15 rounds
// (57.8us kernel @ 80.4% of 8TB/s HBM spec, 65.6us total, rel_err 0.0).
//
// Single fused pass, barrier-free. Every warp independently loads seq_lens
// (32B coalesced; L1-hit after the first warp per SM), shuffle-scans the
// cumsum, resolves its batch via SHFL broadcasts, then streams its half
// token-row: lane l handles base + {0,32,64,96} + l. Fully coalesced
// LDG.128 (.cs, touch-once) with 4 independent loads in flight per thread;
// STG.128 (.wt) bulk stores. 29 regs, no smem, no BAR.
//
// Roofline: traffic at the mandatory floor (256MB writes + ~128MB valid
// reads); achieved bandwidth at the mixed-stream HBM turnaround ceiling
// (78-80% of spec across 9 configurations). Memory-bound, complete.
__global__ void __launch_bounds__(THREADS) pack_kernel(
    const float4* __restrict__ k_src,
    const float4* __restrict__ v_src,
    const int* __restrict__ seq_lens,
    float4* __restrict__ out)
{
    const int lane = threadIdx.x & 31;

    // per-warp cumsum: lane i (i<8) ends with v = sum(seq_lens[0..i])
    int sl = (lane < NB) ? __ldg(seq_lens + lane) : 0;
    int v = sl;
    #pragma unroll
    for (int off = 1; off < NB; off <<= 1) {
        int n = __shfl_up_sync(FULL, v, off);
        if (lane >= off) v += n;
    }
    const int total = __shfl_sync(FULL, v, NB - 1);

    const int gw   = blockIdx.x * WARPS_PER_BLOCK + (threadIdx.x >> 5);
    const int base = gw * F4_PER_WARP;            // warp's first float4 index

    const int which = (base >= CACHE_V) ? 1 : 0;  // whole warp in one cache
    const int j   = base - which * CACHE_V;
    const int row = j >> 8;                        // token-row (shared by all 4 elems)
    const int col = (j & (VPR - 1)) + lane;        // 0 or 128, plus lane

    float4 v0, v1, v2, v3;
    if (row < total) {
        // batch search + offset via shuffle broadcasts of the scan
        int bt = row;                              // t = row - cs[b], cs[0] = 0
        int bi = 0;
        #pragma unroll
        for (int bb = 1; bb < NB; bb++) {
            int csb = __shfl_sync(FULL, v, bb - 1);
            if (row >= csb) { bi = bb; bt = row - csb; }
        }
        const float4* src = (which ? v_src : k_src)
                          + (long long)(bi * NS + bt) * VPR + col;
        v0 = __ldcs(src +  0);
        v1 = __ldcs(src + 32);
        v2 = __ldcs(src + 64);
        v3 = __ldcs(src + 96);
    } else {
        v0 = v1 = v2 = v3 = make_float4(0.f, 0.f, 0.f, 0.f);
    }

    float4* dst = out + base + lane;
    __stwt(dst +  0, v0);
    __stwt(dst + 32, v1);
    __stwt(dst + 64, v2);
    __stwt(dst + 96, v3);

    // scalar tail outputs (block 0, warp 0) — after the bulk stores
    if (blockIdx.x == 0 && threadIdx.x < 32) {
        float* seq_out = (float*)out + 2 * (long long)CACHE_F;  // [NB]
        float* cum_out = seq_out + NB;                           // [NB+1]
        if (lane < NB) {
            seq_out[lane] = (float)sl;
            cum_out[lane + 1] = (float)v;
        }
        if (lane == 0) cum_out[0] = 0.0f;
    }
}

extern "C" void kernel_launch(void* const* d_in, const int* in_sizes, int n_in,
                              void* d_out, int out_size) {
    const float4* key_states   = (const float4*)d_in[0];
    const float4* value_states = (const float4*)d_in[1];
    const int*    seq_lens     = (const int*)d_in[2];

    pack_kernel<<<BLOCKS, THREADS>>>(key_states, value_states, seq_lens,
                                     (float4*)d_out);
}